// round 1
// baseline (speedup 1.0000x reference)
#include <cuda_runtime.h>
#include <cuda_bf16.h>
#include <cstdint>

// Problem constants
#define BB   2
#define CC   128
#define HH   48
#define NTOK 2304          // 48*48
#define NHEADS 8
#define CH   16            // C / heads
#define KTOP 1843          // int(2304 * 0.8)

typedef unsigned long long ull;

// ---------------- scratch (no allocations allowed) ----------------
__device__ float g_q[BB*CC*NTOK];
__device__ float g_k[BB*CC*NTOK];
__device__ float g_v[BB*CC*NTOK];
__device__ float g_attn[BB*CC*NTOK];

// ---------------- packed f32x2 helpers (Blackwell) ----------------
__device__ __forceinline__ ull pk2(float lo, float hi) {
    ull r; asm("mov.b64 %0, {%1, %2};" : "=l"(r) : "f"(lo), "f"(hi)); return r;
}
__device__ __forceinline__ void upk2(ull v, float& lo, float& hi) {
    asm("mov.b64 {%0, %1}, %2;" : "=f"(lo), "=f"(hi) : "l"(v));
}
__device__ __forceinline__ ull ffma2(ull a, ull b, ull c) {
    ull d; asm("fma.rn.f32x2 %0, %1, %2, %3;" : "=l"(d) : "l"(a), "l"(b), "l"(c)); return d;
}

// monotone float->uint key and inverse
__device__ __forceinline__ unsigned fkey(float f) {
    unsigned u = __float_as_uint(f);
    return (u & 0x80000000u) ? ~u : (u | 0x80000000u);
}
__device__ __forceinline__ float kinv(unsigned u) {
    unsigned b = (u & 0x80000000u) ? (u ^ 0x80000000u) : ~u;
    return __uint_as_float(b);
}

// =================================================================
// Kernel 1: qkv = depthwise3x3(pwconv_group4(x, w)), fused per (b,c)
// k gets its per-channel L2 norm (over N) applied here.
// grid = B*C blocks, 256 threads, 9 pixels/thread
// =================================================================
__global__ __launch_bounds__(256) void qkv_kernel(
    const float* __restrict__ x,
    const float* __restrict__ wq, const float* __restrict__ wk, const float* __restrict__ wv,
    const float* __restrict__ dwq, const float* __restrict__ dwk, const float* __restrict__ dwv)
{
    __shared__ float sq[NTOK], sk[NTOK], sv[NTOK];
    __shared__ float wpq[32], wpk[32], wpv[32];
    __shared__ float wdq[9], wdk[9], wdv[9];
    __shared__ float red[256];
    __shared__ float s_scale;

    const int b = blockIdx.x >> 7;
    const int c = blockIdx.x & 127;
    const int g = c >> 5;             // group of 32 input channels
    const int tid = threadIdx.x;

    if (tid < 32) {
        wpq[tid] = wq[c*32 + tid];
        wpk[tid] = wk[c*32 + tid];
        wpv[tid] = wv[c*32 + tid];
    }
    if (tid < 9) {
        wdq[tid] = dwq[c*9 + tid];
        wdk[tid] = dwk[c*9 + tid];
        wdv[tid] = dwv[c*9 + tid];
    }
    __syncthreads();

    // pointwise grouped conv
    const float* xb = x + (size_t)(b*CC + g*32) * NTOK;
    float aq[9], ak[9], av[9];
#pragma unroll
    for (int p = 0; p < 9; ++p) { aq[p] = 0.f; ak[p] = 0.f; av[p] = 0.f; }
    for (int i = 0; i < 32; ++i) {
        const float wq_i = wpq[i], wk_i = wpk[i], wv_i = wpv[i];
        const float* xi = xb + i*NTOK;
#pragma unroll
        for (int p = 0; p < 9; ++p) {
            float xv = xi[tid + p*256];
            aq[p] += wq_i*xv; ak[p] += wk_i*xv; av[p] += wv_i*xv;
        }
    }
#pragma unroll
    for (int p = 0; p < 9; ++p) {
        int n = tid + p*256;
        sq[n] = aq[p]; sk[n] = ak[p]; sv[n] = av[p];
    }
    __syncthreads();

    // depthwise 3x3 SAME (cross-correlation like lax.conv)
    float dq[9], dk[9], dv[9];
    float kss = 0.f;
#pragma unroll
    for (int p = 0; p < 9; ++p) {
        int n = tid + p*256;
        int r = n / HH;
        int col = n - r*HH;
        float s0 = 0.f, s1 = 0.f, s2 = 0.f;
#pragma unroll
        for (int dy = 0; dy < 3; ++dy) {
            int rr = r + dy - 1;
            if ((unsigned)rr < (unsigned)HH) {
#pragma unroll
                for (int dx = 0; dx < 3; ++dx) {
                    int cc2 = col + dx - 1;
                    if ((unsigned)cc2 < (unsigned)HH) {
                        int nn = rr*HH + cc2;
                        s0 += wdq[dy*3+dx] * sq[nn];
                        s1 += wdk[dy*3+dx] * sk[nn];
                        s2 += wdv[dy*3+dx] * sv[nn];
                    }
                }
            }
        }
        dq[p] = s0; dk[p] = s1; dv[p] = s2;
        kss += s1 * s1;
    }

    // block reduce k sum of squares -> per-channel L2 norm over N
    red[tid] = kss;
    __syncthreads();
#pragma unroll
    for (int s = 128; s > 0; s >>= 1) {
        if (tid < s) red[tid] += red[tid + s];
        __syncthreads();
    }
    if (tid == 0) s_scale = 1.f / fmaxf(sqrtf(red[0]), 1e-12f);
    __syncthreads();
    const float sc = s_scale;

    const size_t base = (size_t)(b*CC + c) * NTOK;
#pragma unroll
    for (int p = 0; p < 9; ++p) {
        int n = tid + p*256;
        g_q[base + n] = dq[p];
        g_k[base + n] = dk[p] * sc;
        g_v[base + n] = dv[p];
    }
}

// =================================================================
// Kernel 2: fused attention: scores -> exact top-k select -> softmax -> PV
// grid = (NTOK/16 row tiles, B*NHEADS), 512 threads (16 warps, warp==row)
// dyn smem: scores[16][2304] f32 + q + V chunk + radix hist
// =================================================================
#define ATTN_SMEM_FLOATS (16*NTOK + 256 + 256*18 + 16*256)
#define ATTN_SMEM_BYTES  (ATTN_SMEM_FLOATS * 4)

__global__ __launch_bounds__(512) void attn_kernel(const float* __restrict__ temperature)
{
    extern __shared__ float sm[];
    float* scores = sm;                      // 16 * 2304
    float* qspf   = sm + 16*NTOK;            // [c][r] packed-pair layout, 256
    float* vsf    = qspf + 256;              // V chunk, [jj][18] (16 used + pad)
    int*   hist   = (int*)(vsf + 256*18);    // 16 warps * 256 bins

    const int rt  = blockIdx.x;
    const int bh  = blockIdx.y;
    const int b   = bh >> 3;
    const int h   = bh & 7;
    const int bc0 = b*CC + h*CH;
    const int row0 = rt * 16;
    const int tid = threadIdx.x;
    const float ts = temperature[h];

    // ---- load Q rows, L2-normalize over C_h=16 ----
    if (tid < 256) {
        int r = tid >> 4, c = tid & 15;
        float qv = g_q[(size_t)(bc0 + c)*NTOK + row0 + r];
        float ss = qv * qv;
#pragma unroll
        for (int off = 8; off; off >>= 1) ss += __shfl_xor_sync(0xffffffffu, ss, off, 16);
        qspf[c*16 + r] = qv / fmaxf(sqrtf(ss), 1e-12f);
    }
    __syncthreads();

    // ---- scores: S[16][2304] = Qn @ K, packed f32x2 over row pairs ----
    const float* kb = g_k + (size_t)bc0 * NTOK;
    for (int j = tid; j < NTOK; j += 512) {
        ull acc[8];
#pragma unroll
        for (int rp = 0; rp < 8; ++rp) acc[rp] = 0ull;
#pragma unroll
        for (int c = 0; c < 16; ++c) {
            float kv = kb[c*NTOK + j];
            ull kv2 = pk2(kv, kv);
            const ull* q2 = reinterpret_cast<const ull*>(qspf + c*16);
#pragma unroll
            for (int rp = 0; rp < 8; ++rp) acc[rp] = ffma2(q2[rp], kv2, acc[rp]);
        }
#pragma unroll
        for (int rp = 0; rp < 8; ++rp) {
            float lo, hi; upk2(acc[rp], lo, hi);
            scores[(2*rp)*NTOK + j]   = lo * ts;
            scores[(2*rp+1)*NTOK + j] = hi * ts;
        }
    }
    __syncthreads();

    const int w = tid >> 5, lane = tid & 31;
    float* srow = scores + w*NTOK;

    // ---- row max ----
    float m = -3.4e38f;
    for (int j = lane; j < NTOK; j += 32) m = fmaxf(m, srow[j]);
#pragma unroll
    for (int off = 16; off; off >>= 1) m = fmaxf(m, __shfl_xor_sync(0xffffffffu, m, off));

    // ---- exact k-th largest via 4-pass MSB radix select (per warp) ----
    int* hw = hist + w*256;
    unsigned msk = 0, prefix = 0;
    int kk = KTOP;
    for (int shift = 24; shift >= 0; shift -= 8) {
        for (int i = lane; i < 256; i += 32) hw[i] = 0;
        __syncwarp();
        for (int j = lane; j < NTOK; j += 32) {
            unsigned u = fkey(srow[j]);
            if ((u & msk) == prefix) atomicAdd(hw + ((u >> shift) & 255), 1);
        }
        __syncwarp();
        int d = 0, kk2 = 0;
        if (lane == 0) {
            int cum = 0; d = 256;
            do { --d; cum += hw[d]; } while (cum < kk && d > 0);
            kk2 = kk - (cum - hw[d]);
        }
        d  = __shfl_sync(0xffffffffu, d, 0);
        kk = __shfl_sync(0xffffffffu, kk2, 0);
        prefix |= (unsigned)d << shift;
        msk    |= 0xFFu << shift;
        __syncwarp();
    }
    const float t = kinv(prefix);

    // ---- masked softmax weights in-place, accumulate Z ----
    float z = 0.f;
    for (int j = lane; j < NTOK; j += 32) {
        float s = srow[j];
        float wv = (s >= t) ? __expf(s - m) : 0.f;
        srow[j] = wv;
        z += wv;
    }
#pragma unroll
    for (int off = 16; off; off >>= 1) z += __shfl_xor_sync(0xffffffffu, z, off);

    // ---- PV: out[r][16] = W[r] @ V, V staged through smem in 256-col chunks ----
    const float* vb = g_v + (size_t)bc0 * NTOK;
    ull acc2[8];
#pragma unroll
    for (int cp = 0; cp < 8; ++cp) acc2[cp] = 0ull;

    for (int chunk = 0; chunk < 9; ++chunk) {
        const int j0 = chunk * 256;
        __syncthreads();   // previous chunk fully consumed
        for (int l = tid; l < 4096; l += 512) {
            int cc2 = l >> 8, jj = l & 255;
            vsf[jj*18 + cc2] = vb[cc2*NTOK + j0 + jj];
        }
        __syncthreads();
        for (int jj = lane; jj < 256; jj += 32) {
            float wv = srow[j0 + jj];
            if (wv != 0.f) {
                ull w2 = pk2(wv, wv);
                const ull* vr = reinterpret_cast<const ull*>(vsf + jj*18);
#pragma unroll
                for (int cp = 0; cp < 8; ++cp) acc2[cp] = ffma2(vr[cp], w2, acc2[cp]);
            }
        }
    }

    // ---- warp reduce 16 channel sums, write out ----
    float a16[16];
#pragma unroll
    for (int cp = 0; cp < 8; ++cp) upk2(acc2[cp], a16[2*cp], a16[2*cp+1]);
#pragma unroll
    for (int i = 0; i < 16; ++i) {
#pragma unroll
        for (int off = 16; off; off >>= 1) a16[i] += __shfl_xor_sync(0xffffffffu, a16[i], off);
    }
    const float invz = 1.f / z;
    const int rowg = row0 + w;
#pragma unroll
    for (int i = 0; i < 16; ++i)
        if (lane == i) g_attn[(size_t)(bc0 + i)*NTOK + rowg] = a16[i] * invz;
}

// =================================================================
// Kernel 3: out = x + wo(128x128) @ attn_out   (1x1 conv + residual)
// grid = (N/32, B), 256 threads. wo staged in smem, f32x2 over c-pairs.
// =================================================================
#define OC_SMEM_FLOATS (16384 + 32*130)
#define OC_SMEM_BYTES  (OC_SMEM_FLOATS * 4)

__global__ __launch_bounds__(256) void outconv_kernel(
    const float* __restrict__ x, const float* __restrict__ wo, float* __restrict__ out)
{
    extern __shared__ float sm3[];
    float* wo_s = sm3;             // 128*128
    float* af   = sm3 + 16384;     // transposed attn tile [n(32)][c(128)] stride 130

    const int b  = blockIdx.y;
    const int n0 = blockIdx.x * 32;
    const int tid = threadIdx.x;

    for (int l = tid; l < 16384; l += 256) wo_s[l] = wo[l];
    for (int l = tid; l < 4096; l += 256) {
        int cc2 = l >> 5, nl = l & 31;
        af[nl*130 + cc2] = g_attn[(size_t)(b*CC + cc2)*NTOK + n0 + nl];
    }
    __syncthreads();

    const int lane = tid & 31;
    const int w = tid >> 5;          // warp = c_out group of 16
    const ull* arow = reinterpret_cast<const ull*>(af + lane*130);
    const ull* wou = reinterpret_cast<const ull*>(wo_s);

    ull acc[16];
#pragma unroll
    for (int k = 0; k < 16; ++k) acc[k] = 0ull;

    for (int cp = 0; cp < 64; ++cp) {
        ull av2 = arow[cp];
#pragma unroll
        for (int k = 0; k < 16; ++k)
            acc[k] = ffma2(wou[(w*16 + k)*64 + cp], av2, acc[k]);
    }

#pragma unroll
    for (int k = 0; k < 16; ++k) {
        float lo, hi; upk2(acc[k], lo, hi);
        float s = lo + hi;
        int co = w*16 + k;
        size_t idx = (size_t)(b*CC + co)*NTOK + n0 + lane;
        out[idx] = x[idx] + s;
    }
}

// =================================================================
extern "C" void kernel_launch(void* const* d_in, const int* in_sizes, int n_in,
                              void* d_out, int out_size)
{
    const float* x    = (const float*)d_in[0];
    const float* wq   = (const float*)d_in[1];
    const float* wk   = (const float*)d_in[2];
    const float* wv   = (const float*)d_in[3];
    const float* dwq  = (const float*)d_in[4];
    const float* dwk  = (const float*)d_in[5];
    const float* dwv  = (const float*)d_in[6];
    const float* wo   = (const float*)d_in[7];
    const float* temp = (const float*)d_in[8];
    float* out = (float*)d_out;

    cudaFuncSetAttribute(attn_kernel, cudaFuncAttributeMaxDynamicSharedMemorySize, ATTN_SMEM_BYTES);
    cudaFuncSetAttribute(outconv_kernel, cudaFuncAttributeMaxDynamicSharedMemorySize, OC_SMEM_BYTES);

    qkv_kernel<<<BB*CC, 256>>>(x, wq, wk, wv, dwq, dwk, dwv);
    attn_kernel<<<dim3(NTOK/16, BB*NHEADS), 512, ATTN_SMEM_BYTES>>>(temp);
    outconv_kernel<<<dim3(NTOK/32, BB), 256, OC_SMEM_BYTES>>>(x, wo, out);
}

// round 2
// speedup vs baseline: 3.3604x; 3.3604x over previous
#include <cuda_runtime.h>
#include <cuda_bf16.h>
#include <cstdint>

// Problem constants
#define BB   2
#define CC   128
#define HH   48
#define NTOK 2304          // 48*48
#define NHEADS 8
#define CHH  16            // C / heads
#define KTOP 1843          // int(2304 * 0.8)

typedef unsigned long long ull;

// ---------------- scratch (no allocations allowed) ----------------
__device__ float g_q[BB*CC*NTOK];                      // fp32 q (pre-norm)
__device__ __nv_bfloat16 g_kT[BB*NHEADS*NTOK*CHH];     // normalized K, [bh][n][ch]
__device__ __nv_bfloat16 g_v16[BB*CC*NTOK];            // v bf16, [b*C+c][n]
__device__ float g_attn[BB*CC*NTOK];                   // attention output fp32

// ---------------- packed f32x2 helpers (outconv) ----------------
__device__ __forceinline__ ull pk2(float lo, float hi) {
    ull r; asm("mov.b64 %0, {%1, %2};" : "=l"(r) : "f"(lo), "f"(hi)); return r;
}
__device__ __forceinline__ void upk2(ull v, float& lo, float& hi) {
    asm("mov.b64 {%0, %1}, %2;" : "=f"(lo), "=f"(hi) : "l"(v));
}
__device__ __forceinline__ ull ffma2(ull a, ull b, ull c) {
    ull d; asm("fma.rn.f32x2 %0, %1, %2, %3;" : "=l"(d) : "l"(a), "l"(b), "l"(c)); return d;
}

// bf16x2 pack/unpack
__device__ __forceinline__ unsigned pack_bf2(float lo, float hi) {
    unsigned r; asm("cvt.rn.bf16x2.f32 %0, %1, %2;" : "=r"(r) : "f"(hi), "f"(lo)); return r;
}
__device__ __forceinline__ float bf_lo(unsigned u) { return __uint_as_float(u << 16); }
__device__ __forceinline__ float bf_hi(unsigned u) { return __uint_as_float(u & 0xffff0000u); }

// monotone 16-bit key for bf16 bits
__device__ __forceinline__ unsigned key16(unsigned u16) {
    return (u16 & 0x8000u) ? (u16 ^ 0xffffu) : (u16 | 0x8000u);
}

__device__ __forceinline__ void mma_bf16(float& c0, float& c1, float& c2, float& c3,
                                         unsigned a0, unsigned a1, unsigned a2, unsigned a3,
                                         unsigned b0, unsigned b1) {
    asm volatile("mma.sync.aligned.m16n8k16.row.col.f32.bf16.bf16.f32 "
                 "{%0,%1,%2,%3}, {%4,%5,%6,%7}, {%8,%9}, {%0,%1,%2,%3};"
                 : "+f"(c0), "+f"(c1), "+f"(c2), "+f"(c3)
                 : "r"(a0), "r"(a1), "r"(a2), "r"(a3), "r"(b0), "r"(b1));
}

// =================================================================
// Kernel 1: qkv = depthwise3x3(pwconv_group4(x, w)), fused per (b,c)
// k gets per-channel L2 norm applied and is written transposed bf16.
// =================================================================
__global__ __launch_bounds__(256) void qkv_kernel(
    const float* __restrict__ x,
    const float* __restrict__ wq, const float* __restrict__ wk, const float* __restrict__ wv,
    const float* __restrict__ dwq, const float* __restrict__ dwk, const float* __restrict__ dwv)
{
    __shared__ float sq[NTOK], sk[NTOK], sv[NTOK];
    __shared__ float wpq[32], wpk[32], wpv[32];
    __shared__ float wdq[9], wdk[9], wdv[9];
    __shared__ float red[256];
    __shared__ float s_scale;

    const int b = blockIdx.x >> 7;
    const int c = blockIdx.x & 127;
    const int g = c >> 5;
    const int tid = threadIdx.x;

    if (tid < 32) {
        wpq[tid] = wq[c*32 + tid];
        wpk[tid] = wk[c*32 + tid];
        wpv[tid] = wv[c*32 + tid];
    }
    if (tid < 9) {
        wdq[tid] = dwq[c*9 + tid];
        wdk[tid] = dwk[c*9 + tid];
        wdv[tid] = dwv[c*9 + tid];
    }
    __syncthreads();

    const float* xb = x + (size_t)(b*CC + g*32) * NTOK;
    float aq[9], ak[9], av[9];
#pragma unroll
    for (int p = 0; p < 9; ++p) { aq[p] = 0.f; ak[p] = 0.f; av[p] = 0.f; }
    for (int i = 0; i < 32; ++i) {
        const float wq_i = wpq[i], wk_i = wpk[i], wv_i = wpv[i];
        const float* xi = xb + i*NTOK;
#pragma unroll
        for (int p = 0; p < 9; ++p) {
            float xv = xi[tid + p*256];
            aq[p] += wq_i*xv; ak[p] += wk_i*xv; av[p] += wv_i*xv;
        }
    }
#pragma unroll
    for (int p = 0; p < 9; ++p) {
        int n = tid + p*256;
        sq[n] = aq[p]; sk[n] = ak[p]; sv[n] = av[p];
    }
    __syncthreads();

    float dq[9], dk[9], dv[9];
    float kss = 0.f;
#pragma unroll
    for (int p = 0; p < 9; ++p) {
        int n = tid + p*256;
        int r = n / HH;
        int col = n - r*HH;
        float s0 = 0.f, s1 = 0.f, s2 = 0.f;
#pragma unroll
        for (int dy = 0; dy < 3; ++dy) {
            int rr = r + dy - 1;
            if ((unsigned)rr < (unsigned)HH) {
#pragma unroll
                for (int dx = 0; dx < 3; ++dx) {
                    int cc2 = col + dx - 1;
                    if ((unsigned)cc2 < (unsigned)HH) {
                        int nn = rr*HH + cc2;
                        s0 += wdq[dy*3+dx] * sq[nn];
                        s1 += wdk[dy*3+dx] * sk[nn];
                        s2 += wdv[dy*3+dx] * sv[nn];
                    }
                }
            }
        }
        dq[p] = s0; dk[p] = s1; dv[p] = s2;
        kss += s1 * s1;
    }

    red[tid] = kss;
    __syncthreads();
#pragma unroll
    for (int s = 128; s > 0; s >>= 1) {
        if (tid < s) red[tid] += red[tid + s];
        __syncthreads();
    }
    if (tid == 0) s_scale = 1.f / fmaxf(sqrtf(red[0]), 1e-12f);
    __syncthreads();
    const float sc = s_scale;

    const size_t base = (size_t)(b*CC + c) * NTOK;
    const int bh = b*NHEADS + (c >> 4);
    const int ch = c & 15;
    __nv_bfloat16* kT = g_kT + (size_t)bh * NTOK * CHH + ch;
#pragma unroll
    for (int p = 0; p < 9; ++p) {
        int n = tid + p*256;
        g_q[base + n] = dq[p];
        kT[(size_t)n * CHH] = __float2bfloat16(dk[p] * sc);
        g_v16[base + n] = __float2bfloat16(dv[p]);
    }
}

// =================================================================
// Kernel 2: fused attention, tensor-core bf16.
// grid = (NTOK/16 row tiles, B*NHEADS), 512 threads (16 warps)
// =================================================================
#define SROW_U32 1156                      // 1152 + 4 pad (bank spread)
#define ATTN_SM_S    (16*SROW_U32*4)       // 73984 bf16 scores/weights
#define ATTN_SM_QA   512                   // 16x16 bf16 A fragment source
#define ATTN_SM_HIST (16*256*4)            // radix hist / PV reduce scratch
#define ATTN_SM_RST  64                    // invz[16]
#define ATTN_SMEM_BYTES (ATTN_SM_S + ATTN_SM_QA + ATTN_SM_HIST + ATTN_SM_RST)

// parallel "find bin from top" over 256 bins; updates kk, returns bin
__device__ __forceinline__ unsigned find_bin(const unsigned* hw, int lane, int& kk) {
    int base = lane * 8;
    unsigned l[8];
    int ls = 0;
#pragma unroll
    for (int i = 0; i < 8; ++i) { l[i] = hw[base + i]; ls += l[i]; }
    int suf = ls;
#pragma unroll
    for (int off = 1; off < 32; off <<= 1) {
        int v = __shfl_down_sync(0xffffffffu, suf, off);
        if (lane + off < 32) suf += v;
    }
    int above = suf - ls;
    bool found = (suf >= kk) && (above < kk);
    unsigned bal = __ballot_sync(0xffffffffu, found);
    int fl = __ffs(bal) - 1;
    int dloc = 0, kkloc = 0;
    if (found) {
        int cum = above;
#pragma unroll
        for (int i = 7; i >= 0; --i) {
            cum += (int)l[i];
            if (cum >= kk) { dloc = base + i; kkloc = kk - (cum - (int)l[i]); break; }
        }
    }
    unsigned d = (unsigned)__shfl_sync(0xffffffffu, dloc, fl);
    kk = __shfl_sync(0xffffffffu, kkloc, fl);
    return d;
}

__global__ __launch_bounds__(512, 2) void attn_kernel(const float* __restrict__ temperature)
{
    extern __shared__ unsigned char smraw[];
    unsigned* sU = (unsigned*)smraw;                               // scores/weights u32 view
    __nv_bfloat16* qA = (__nv_bfloat16*)(smraw + ATTN_SM_S);       // [16][16]
    unsigned* hist = (unsigned*)(smraw + ATTN_SM_S + ATTN_SM_QA);  // [16][256]
    float* scratch = (float*)hist;                                 // alias (after select)
    float* invz = (float*)(smraw + ATTN_SM_S + ATTN_SM_QA + ATTN_SM_HIST);

    const int rt = blockIdx.x, bh = blockIdx.y;
    const int b = bh >> 3, h = bh & 7;
    const int bc0 = b*CC + h*CHH;
    const int row0 = rt * 16;
    const int tid = threadIdx.x;
    const int w = tid >> 5, lane = tid & 31;
    const float ts = temperature[h];

    // ---- phase 0: load Q rows, L2-normalize over C_h, fold temperature ----
    if (tid < 256) {
        int r = tid >> 4, c = tid & 15;
        float qv = g_q[(size_t)(bc0 + c)*NTOK + row0 + r];
        float ss = qv * qv;
#pragma unroll
        for (int off = 8; off; off >>= 1) ss += __shfl_xor_sync(0xffffffffu, ss, off, 16);
        qA[r*16 + c] = __float2bfloat16(qv * ts / fmaxf(sqrtf(ss), 1e-12f));
    }
    __syncthreads();

    // ---- phase 1: scores via mma, warp w owns cols [w*144, w*144+144) ----
    unsigned a0, a1, a2, a3;
    {
        const unsigned* qAu = (const unsigned*)qA;
        int r = lane >> 2, kx = (lane & 3) * 2;
        a0 = qAu[(r*16 + kx) >> 1];
        a1 = qAu[((r+8)*16 + kx) >> 1];
        a2 = qAu[(r*16 + kx + 8) >> 1];
        a3 = qAu[((r+8)*16 + kx + 8) >> 1];
    }
    {
        const unsigned* kTu = (const unsigned*)(g_kT + (size_t)bh * NTOK * CHH);
        const int jl = lane >> 2, ko = lane & 3;
        const int r = lane >> 2, cst = (lane & 3) * 2;
#pragma unroll 3
        for (int m = 0; m < 18; ++m) {
            int j0 = w*144 + m*8;
            const unsigned* kp = kTu + (size_t)(j0 + jl)*8 + ko;
            unsigned b0 = kp[0];
            unsigned b1 = kp[4];
            float c0 = 0.f, c1 = 0.f, c2 = 0.f, c3 = 0.f;
            mma_bf16(c0, c1, c2, c3, a0, a1, a2, a3, b0, b1);
            int ju = (j0 >> 1) + (cst >> 1);
            sU[r*SROW_U32 + ju]     = pack_bf2(c0, c1);
            sU[(r+8)*SROW_U32 + ju] = pack_bf2(c2, c3);
        }
    }
    __syncthreads();

    // ---- phase 2: per-row (warp) max + 2-pass 8-bit radix select on bf16 keys ----
    unsigned* srowU = sU + w*SROW_U32;
    unsigned* hw = hist + w*256;
#pragma unroll
    for (int i = lane; i < 256; i += 32) hw[i] = 0;
    __syncwarp();

    float rmax = -3.4e38f;
    for (int it = 0; it < 36; ++it) {
        unsigned u = srowU[lane + it*32];
        rmax = fmaxf(rmax, fmaxf(bf_lo(u), bf_hi(u)));
        unsigned h0 = key16(u & 0xffffu) >> 8;
        unsigned h1 = key16(u >> 16) >> 8;
        unsigned mm = __match_any_sync(0xffffffffu, h0);
        if ((mm & ((1u << lane) - 1u)) == 0) atomicAdd(&hw[h0], __popc(mm));
        mm = __match_any_sync(0xffffffffu, h1);
        if ((mm & ((1u << lane) - 1u)) == 0) atomicAdd(&hw[h1], __popc(mm));
    }
#pragma unroll
    for (int off = 16; off; off >>= 1) rmax = fmaxf(rmax, __shfl_xor_sync(0xffffffffu, rmax, off));
    __syncwarp();

    int kk = KTOP;
    unsigned dhi = find_bin(hw, lane, kk);

#pragma unroll
    for (int i = lane; i < 256; i += 32) hw[i] = 0;
    __syncwarp();
    for (int it = 0; it < 36; ++it) {
        unsigned u = srowU[lane + it*32];
        unsigned k0 = key16(u & 0xffffu);
        unsigned k1 = key16(u >> 16);
        if ((k0 >> 8) == dhi) atomicAdd(&hw[k0 & 255u], 1u);
        if ((k1 >> 8) == dhi) atomicAdd(&hw[k1 & 255u], 1u);
    }
    __syncwarp();
    unsigned dlo = find_bin(hw, lane, kk);

    unsigned tkey = (dhi << 8) | dlo;
    unsigned tb = (tkey & 0x8000u) ? (tkey ^ 0x8000u) : (tkey ^ 0xffffu);
    const float tthr = __uint_as_float(tb << 16);

    // ---- phase 3: masked softmax weights (bf16, in place), accumulate Z ----
    float z = 0.f;
    for (int it = 0; it < 36; ++it) {
        unsigned u = srowU[lane + it*32];
        float f0 = bf_lo(u), f1 = bf_hi(u);
        float w0 = (f0 >= tthr) ? __expf(f0 - rmax) : 0.f;
        float w1 = (f1 >= tthr) ? __expf(f1 - rmax) : 0.f;
        z += w0 + w1;
        srowU[lane + it*32] = pack_bf2(w0, w1);
    }
#pragma unroll
    for (int off = 16; off; off >>= 1) z += __shfl_xor_sync(0xffffffffu, z, off);
    if (lane == 0) invz[w] = 1.f / z;
    __syncthreads();   // all weights visible; hist region now dead -> scratch

    // ---- phase 4: PV via mma, warp w owns token stripe [w*144, +144) ----
    float acc[8];
#pragma unroll
    for (int i = 0; i < 8; ++i) acc[i] = 0.f;
    {
        const __nv_bfloat16* vb = g_v16 + (size_t)bc0 * NTOK;
        const int r = lane >> 2, kx = (lane & 3) * 2;
#pragma unroll 3
        for (int cnk = 0; cnk < 9; ++cnk) {
            int k0 = w*144 + cnk*16;
            unsigned A0 = sU[r*SROW_U32 + ((k0 + kx) >> 1)];
            unsigned A1 = sU[(r+8)*SROW_U32 + ((k0 + kx) >> 1)];
            unsigned A2 = sU[r*SROW_U32 + ((k0 + kx + 8) >> 1)];
            unsigned A3 = sU[(r+8)*SROW_U32 + ((k0 + kx + 8) >> 1)];
            unsigned B0 = *(const unsigned*)(vb + (size_t)r*NTOK + k0 + kx);
            unsigned B1 = *(const unsigned*)(vb + (size_t)r*NTOK + k0 + kx + 8);
            mma_bf16(acc[0], acc[1], acc[2], acc[3], A0, A1, A2, A3, B0, B1);
            unsigned B2 = *(const unsigned*)(vb + (size_t)(r+8)*NTOK + k0 + kx);
            unsigned B3 = *(const unsigned*)(vb + (size_t)(r+8)*NTOK + k0 + kx + 8);
            mma_bf16(acc[4], acc[5], acc[6], acc[7], A0, A1, A2, A3, B2, B3);
        }
    }
    {
        int r = lane >> 2, c2 = (lane & 3) * 2;
        float* sw = scratch + w*256;
        sw[r*16 + c2]           = acc[0];
        sw[r*16 + c2 + 1]       = acc[1];
        sw[(r+8)*16 + c2]       = acc[2];
        sw[(r+8)*16 + c2 + 1]   = acc[3];
        sw[r*16 + 8 + c2]       = acc[4];
        sw[r*16 + 8 + c2 + 1]   = acc[5];
        sw[(r+8)*16 + 8 + c2]   = acc[6];
        sw[(r+8)*16 + 8 + c2+1] = acc[7];
    }
    __syncthreads();

    // ---- phase 5: cross-warp reduce + write ----
    if (tid < 256) {
        int r = tid >> 4, c = tid & 15;
        float s = 0.f;
#pragma unroll
        for (int wi = 0; wi < 16; ++wi) s += scratch[wi*256 + r*16 + c];
        g_attn[(size_t)(bc0 + c)*NTOK + row0 + r] = s * invz[r];
    }
}

// =================================================================
// Kernel 3: out = x + wo(128x128) @ attn_out   (1x1 conv + residual)
// =================================================================
#define OC_SMEM_FLOATS (16384 + 32*130)
#define OC_SMEM_BYTES  (OC_SMEM_FLOATS * 4)

__global__ __launch_bounds__(256) void outconv_kernel(
    const float* __restrict__ x, const float* __restrict__ wo, float* __restrict__ out)
{
    extern __shared__ float sm3[];
    float* wo_s = sm3;             // 128*128
    float* af   = sm3 + 16384;     // transposed attn tile [n(32)][c(128)] stride 130

    const int b  = blockIdx.y;
    const int n0 = blockIdx.x * 32;
    const int tid = threadIdx.x;

    for (int l = tid; l < 16384; l += 256) wo_s[l] = wo[l];
    for (int l = tid; l < 4096; l += 256) {
        int cc2 = l >> 5, nl = l & 31;
        af[nl*130 + cc2] = g_attn[(size_t)(b*CC + cc2)*NTOK + n0 + nl];
    }
    __syncthreads();

    const int lane = tid & 31;
    const int w = tid >> 5;
    const ull* arow = reinterpret_cast<const ull*>(af + lane*130);
    const ull* wou = reinterpret_cast<const ull*>(wo_s);

    ull acc[16];
#pragma unroll
    for (int k = 0; k < 16; ++k) acc[k] = 0ull;

    for (int cp = 0; cp < 64; ++cp) {
        ull av2 = arow[cp];
#pragma unroll
        for (int k = 0; k < 16; ++k)
            acc[k] = ffma2(wou[(w*16 + k)*64 + cp], av2, acc[k]);
    }

#pragma unroll
    for (int k = 0; k < 16; ++k) {
        float lo, hi; upk2(acc[k], lo, hi);
        float s = lo + hi;
        int co = w*16 + k;
        size_t idx = (size_t)(b*CC + co)*NTOK + n0 + lane;
        out[idx] = x[idx] + s;
    }
}

// =================================================================
extern "C" void kernel_launch(void* const* d_in, const int* in_sizes, int n_in,
                              void* d_out, int out_size)
{
    const float* x    = (const float*)d_in[0];
    const float* wq   = (const float*)d_in[1];
    const float* wk   = (const float*)d_in[2];
    const float* wv   = (const float*)d_in[3];
    const float* dwq  = (const float*)d_in[4];
    const float* dwk  = (const float*)d_in[5];
    const float* dwv  = (const float*)d_in[6];
    const float* wo   = (const float*)d_in[7];
    const float* temp = (const float*)d_in[8];
    float* out = (float*)d_out;

    cudaFuncSetAttribute(attn_kernel, cudaFuncAttributeMaxDynamicSharedMemorySize, ATTN_SMEM_BYTES);
    cudaFuncSetAttribute(outconv_kernel, cudaFuncAttributeMaxDynamicSharedMemorySize, OC_SMEM_BYTES);

    qkv_kernel<<<BB*CC, 256>>>(x, wq, wk, wv, dwq, dwk, dwv);
    attn_kernel<<<dim3(NTOK/16, BB*NHEADS), 512, ATTN_SMEM_BYTES>>>(temp);
    outconv_kernel<<<dim3(NTOK/32, BB), 256, OC_SMEM_BYTES>>>(x, wo, out);
}